// round 12
// baseline (speedup 1.0000x reference)
#include <cuda_runtime.h>
#include <cuda_bf16.h>
#include <math.h>

// CoxPHLoss without sorting, single cooperative kernel:
//   S[t]  = sum_{j: time_j == t} exp(risk_j)         (4096 buckets)
//   L[t]  = log( sum_{t' >= t} S[t'] )               (suffix logsum)
//   nll   = sum_t d_t * L[t] - sum_{i: event_i} risk_i
//
// KEY CHANGE vs prior rounds: the histogram is accumulated with GLOBAL
// integer RED (no-return atomics) straight into a 32KB L2-resident array,
// bypassing the per-SM shared-atomic pipe (measured binding at ~2 cyc/lane,
// ~100us). L2 LTS slices process spread-address REDs in parallel chip-wide.
// u32 fixed point (2^12) => integer adds => deterministic.
//
// grid = 296 (2/SM via launch_bounds) -> all blocks co-resident -> spin
// barrier is safe. Block 0 does the suffix scan + NLL and self-cleans the
// accumulators for the next graph replay.

#define NBINS    4096
#define GRIDC    296
#define THREADS1 1024
#define FIX_SCALE 4096.0f                 // 2^12
#define FIX_INV   2.44140625e-04          // 2^-12 exact

// Scratch (device globals; zero at load, self-cleaned per launch)
__device__ unsigned int g_Sfix[NBINS];    // fixed-point bucket exp-sums
__device__ unsigned int g_D[NBINS];       // bucket event counts
__device__ double       g_partER[GRIDC];  // per-block sum of event risks
__device__ unsigned int g_bar1;

__global__ __launch_bounds__(THREADS1, 2)
void cox_redg_kernel(const float* __restrict__ risk,
                     const int* __restrict__ time_,
                     const int* __restrict__ event_,
                     float* __restrict__ out,
                     int n)
{
    __shared__ double s_red[32];
    __shared__ long long s_dred[32];
    __shared__ double warpSums[32];
    __shared__ double pref[NBINS];        // block-0 final phase only (32 KB)

    const int tid = threadIdx.x;
    const int bid = blockIdx.x;
    const int lane = tid & 31, wid = tid >> 5;

    // ---------------- Phase 1: stream + global RED histogram ------------
    double er = 0.0;   // sum of risk over events (this thread)

    const int nvec = n >> 2;
    const float4* r4 = reinterpret_cast<const float4*>(risk);
    const int4*   t4 = reinterpret_cast<const int4*>(time_);
    const int4*   e4 = reinterpret_cast<const int4*>(event_);

    const int gstride = GRIDC * THREADS1;
    const int gtid = bid * THREADS1 + tid;

    for (int i = gtid; i < nvec; i += gstride) {
        float4 r = r4[i];
        int4   t = t4[i];
        int4   e = e4[i];

        int t0 = t.x & (NBINS - 1);
        int t1 = t.y & (NBINS - 1);
        int t2 = t.z & (NBINS - 1);
        int t3 = t.w & (NBINS - 1);

        unsigned int v0 = __float2uint_rn(__expf(r.x) * FIX_SCALE);
        unsigned int v1 = __float2uint_rn(__expf(r.y) * FIX_SCALE);
        unsigned int v2 = __float2uint_rn(__expf(r.z) * FIX_SCALE);
        unsigned int v3 = __float2uint_rn(__expf(r.w) * FIX_SCALE);

        atomicAdd(&g_Sfix[t0], v0);   // result unused -> RED (no return)
        atomicAdd(&g_Sfix[t1], v1);
        atomicAdd(&g_Sfix[t2], v2);
        atomicAdd(&g_Sfix[t3], v3);

        if (e.x) { atomicAdd(&g_D[t0], 1u); er += (double)r.x; }
        if (e.y) { atomicAdd(&g_D[t1], 1u); er += (double)r.y; }
        if (e.z) { atomicAdd(&g_D[t2], 1u); er += (double)r.z; }
        if (e.w) { atomicAdd(&g_D[t3], 1u); er += (double)r.w; }
    }

    // scalar tail (n not multiple of 4)
    for (int j = (nvec << 2) + gtid; j < n; j += gstride) {
        float r = risk[j];
        int   t = time_[j] & (NBINS - 1);
        atomicAdd(&g_Sfix[t], __float2uint_rn(__expf(r) * FIX_SCALE));
        if (event_[j]) { atomicAdd(&g_D[t], 1u); er += (double)r; }
    }

    // block-reduce er -> g_partER[bid]
    #pragma unroll
    for (int off = 16; off > 0; off >>= 1)
        er += __shfl_down_sync(0xffffffffu, er, off);
    if (lane == 0) s_red[wid] = er;
    __syncthreads();
    if (wid == 0) {
        double v = s_red[lane];
        #pragma unroll
        for (int off = 16; off > 0; off >>= 1)
            v += __shfl_down_sync(0xffffffffu, v, off);
        if (lane == 0) g_partER[bid] = v;
    }

    // ---------------- grid barrier (arrive; only block 0 waits) ---------
    __threadfence();
    __syncthreads();
    if (tid == 0)
        atomicAdd(&g_bar1, 1u);
    if (bid != 0)
        return;
    if (tid == 0) {
        while (atomicAdd(&g_bar1, 0u) < GRIDC)
            __nanosleep(64);
    }
    __syncthreads();

    // ---------------- Phase 2: suffix scan + NLL (block 0) --------------
    const int base = tid * 4;   // 4 reversed-index elements per thread

    double v[4];
    int dloc[4];
    double run = 0.0;
    #pragma unroll
    for (int k = 0; k < 4; k++) {
        int t = NBINS - 1 - (base + k);
        run += (double)g_Sfix[t] * FIX_INV;
        v[k] = run;
        dloc[k] = (int)g_D[t];
    }
    double total = run;

    // warp inclusive scan of per-thread totals
    double x = total;
    #pragma unroll
    for (int off = 1; off < 32; off <<= 1) {
        double y = __shfl_up_sync(0xffffffffu, x, off);
        if (lane >= off) x += y;
    }
    double wexcl = x - total;
    if (lane == 31) warpSums[wid] = x;
    __syncthreads();

    if (wid == 0) {
        double ws = warpSums[lane];
        double xx = ws;
        #pragma unroll
        for (int off = 1; off < 32; off <<= 1) {
            double y = __shfl_up_sync(0xffffffffu, xx, off);
            if (lane >= off) xx += y;
        }
        warpSums[lane] = xx - ws;   // exclusive warp offsets
    }
    __syncthreads();

    double off0 = warpSums[wid] + wexcl;
    #pragma unroll
    for (int k = 0; k < 4; k++)
        pref[base + k] = off0 + v[k];
    __syncthreads();

    // d_t * log(suffix_sum[t]); suffix_sum[t] = pref[4095 - t]
    double c = 0.0;
    long long dtot = 0;
    #pragma unroll
    for (int k = 0; k < 4; k++) {
        int j = base + k;
        int d = dloc[k];
        dtot += d;
        if (d > 0) c += (double)d * log(pref[j]);
    }
    // subtract event-risk sum (fixed order across tid => deterministic)
    if (tid < GRIDC) c -= g_partER[tid];

    #pragma unroll
    for (int off = 16; off > 0; off >>= 1) {
        c    += __shfl_down_sync(0xffffffffu, c, off);
        dtot += __shfl_down_sync(0xffffffffu, dtot, off);
    }
    if (lane == 0) { s_red[wid] = c; s_dred[wid] = dtot; }
    __syncthreads();
    if (wid == 0) {
        double cc = s_red[lane];
        long long dd = s_dred[lane];
        #pragma unroll
        for (int off = 16; off > 0; off >>= 1) {
            cc += __shfl_down_sync(0xffffffffu, cc, off);
            dd += __shfl_down_sync(0xffffffffu, dd, off);
        }
        if (lane == 0)
            out[0] = (dd > 0) ? (float)cc : 0.0f;
    }
    __syncthreads();

    // self-clean accumulators for the next graph replay
    #pragma unroll
    for (int i = tid; i < NBINS; i += THREADS1) {
        g_Sfix[i] = 0u;
        g_D[i] = 0u;
    }
    if (tid == 0)
        g_bar1 = 0u;
}

// ---------------------------------------------------------------------------
extern "C" void kernel_launch(void* const* d_in, const int* in_sizes, int n_in,
                              void* d_out, int out_size)
{
    const float* risk  = (const float*)d_in[0];
    const int*   time_ = (const int*)d_in[1];
    const int*   event_= (const int*)d_in[2];
    float* out = (float*)d_out;
    int n = in_sizes[0];

    cox_redg_kernel<<<GRIDC, THREADS1>>>(risk, time_, event_, out, n);
}

// round 13
// speedup vs baseline: 3.3829x; 3.3829x over previous
#include <cuda_runtime.h>
#include <cuda_bf16.h>
#include <math.h>

// CoxPHLoss without sorting, fused single kernel:
//   S[t]  = sum_{j: time_j == t} exp(risk_j)         (4096 buckets)
//   L[t]  = log( sum_{t' >= t} S[t'] )               (suffix logsum)
//   nll   = sum_t d_t * L[t] - sum_{i: event_i} risk_i
//
// Histogram: ONE packed 32-bit shared atomic per element:
//   v = fix11(exp(r)) | (event << 25)
// -> 8.4M atomic lanes instead of 12.6M (the smem-ATOMS pipe is the measured
//    bottleneck at ~2 cyc/lane/SM). 25-bit S field (50x margin per block-bin
//    cell), 7-bit event-count field (4x margin).
// Global combine: exact integer atomics at the same 2^11 scale (u64) ->
// deterministic. Last block does the suffix scan + NLL and self-cleans.

#define NBINS    4096
#define GRID1    296            // 2 blocks/SM x 148 SMs
#define THREADS1 1024
#define FIX_SCALE 2048.0f               // 2^11
#define FIX_INV   4.8828125e-04         // 2^-11 exact
#define DSHIFT    25
#define SMASK     ((1u << DSHIFT) - 1u)

// Scratch (device globals; zero at load, self-cleaned per launch)
__device__ unsigned long long g_Sfix[NBINS];
__device__ int                g_D[NBINS];
__device__ double             g_partER[GRID1];
__device__ unsigned int       g_count;

union SmemU {
    unsigned int P[NBINS];  // packed (D<<25)|Sfix   (16 KB)
    double pref[NBINS / 2]; // final-phase alias (first half)
};

__global__ __launch_bounds__(THREADS1, 2)
void cox_fused_kernel(const float* __restrict__ risk,
                      const int* __restrict__ time_,
                      const int* __restrict__ event_,
                      float* __restrict__ out,
                      int n)
{
    __shared__ unsigned int s_P[NBINS];   // packed histogram (16 KB)
    __shared__ double pref[NBINS];        // final phase (32 KB) - only block
                                          // ~last uses it, but must be static
    __shared__ double s_red[32];
    __shared__ long long s_dred[32];
    __shared__ double warpSums[32];
    __shared__ unsigned int s_ticket;

    const int tid = threadIdx.x;
    const int bid = blockIdx.x;
    const int lane = tid & 31, wid = tid >> 5;

    #pragma unroll
    for (int i = tid; i < NBINS; i += THREADS1)
        s_P[i] = 0u;
    __syncthreads();

    // ---------------- Phase 1: streaming packed histogram ----------------
    double er = 0.0;   // sum of risk over events (this thread)

    const int nvec = n >> 2;
    const float4* r4 = reinterpret_cast<const float4*>(risk);
    const int4*   t4 = reinterpret_cast<const int4*>(time_);
    const int4*   e4 = reinterpret_cast<const int4*>(event_);

    const int gstride = GRID1 * THREADS1;
    const int gtid = bid * THREADS1 + tid;

    for (int i = gtid; i < nvec; i += gstride) {
        float4 r = r4[i];
        int4   t = t4[i];
        int4   e = e4[i];

        int t0 = t.x & (NBINS - 1);
        int t1 = t.y & (NBINS - 1);
        int t2 = t.z & (NBINS - 1);
        int t3 = t.w & (NBINS - 1);

        unsigned int v0 = __float2uint_rn(__expf(r.x) * FIX_SCALE);
        unsigned int v1 = __float2uint_rn(__expf(r.y) * FIX_SCALE);
        unsigned int v2 = __float2uint_rn(__expf(r.z) * FIX_SCALE);
        unsigned int v3 = __float2uint_rn(__expf(r.w) * FIX_SCALE);

        if (e.x) { v0 += (1u << DSHIFT); er += (double)r.x; }
        if (e.y) { v1 += (1u << DSHIFT); er += (double)r.y; }
        if (e.z) { v2 += (1u << DSHIFT); er += (double)r.z; }
        if (e.w) { v3 += (1u << DSHIFT); er += (double)r.w; }

        atomicAdd(&s_P[t0], v0);
        atomicAdd(&s_P[t1], v1);
        atomicAdd(&s_P[t2], v2);
        atomicAdd(&s_P[t3], v3);
    }

    // scalar tail (n not multiple of 4)
    for (int j = (nvec << 2) + gtid; j < n; j += gstride) {
        float r = risk[j];
        int   t = time_[j] & (NBINS - 1);
        unsigned int v = __float2uint_rn(__expf(r) * FIX_SCALE);
        if (event_[j]) { v += (1u << DSHIFT); er += (double)r; }
        atomicAdd(&s_P[t], v);
    }

    // block-reduce er -> g_partER[bid]
    #pragma unroll
    for (int off = 16; off > 0; off >>= 1)
        er += __shfl_down_sync(0xffffffffu, er, off);
    if (lane == 0) s_red[wid] = er;
    __syncthreads();
    if (wid == 0) {
        double v = s_red[lane];
        #pragma unroll
        for (int off = 16; off > 0; off >>= 1)
            v += __shfl_down_sync(0xffffffffu, v, off);
        if (lane == 0) g_partER[bid] = v;
    }
    __syncthreads();

    // flush packed histogram -> global integer accumulators (same 2^11
    // scale, exact integer adds -> deterministic)
    #pragma unroll
    for (int i = tid; i < NBINS; i += THREADS1) {
        unsigned int p = s_P[i];
        if (p) {
            unsigned int sfx = p & SMASK;
            int d = (int)(p >> DSHIFT);
            atomicAdd(&g_Sfix[i], (unsigned long long)sfx);
            if (d) atomicAdd(&g_D[i], d);
        }
    }

    // ---- last-block-done: final suffix scan + NLL + self-clean ----
    __threadfence();
    __syncthreads();
    if (tid == 0)
        s_ticket = atomicAdd(&g_count, 1u);
    __syncthreads();
    if (s_ticket != GRID1 - 1)
        return;

    // Last block: all other blocks' atomics visible.
    const int base = tid * 4;   // 4 reversed-index elements per thread

    double v[4];
    int dloc[4];
    double run = 0.0;
    #pragma unroll
    for (int k = 0; k < 4; k++) {
        int t = NBINS - 1 - (base + k);
        run += (double)g_Sfix[t] * FIX_INV;
        v[k] = run;
        dloc[k] = g_D[t];
    }
    double total = run;

    // warp inclusive scan of per-thread totals
    double x = total;
    #pragma unroll
    for (int off = 1; off < 32; off <<= 1) {
        double y = __shfl_up_sync(0xffffffffu, x, off);
        if (lane >= off) x += y;
    }
    double wexcl = x - total;
    if (lane == 31) warpSums[wid] = x;
    __syncthreads();

    if (wid == 0) {
        double ws = warpSums[lane];
        double xx = ws;
        #pragma unroll
        for (int off = 1; off < 32; off <<= 1) {
            double y = __shfl_up_sync(0xffffffffu, xx, off);
            if (lane >= off) xx += y;
        }
        warpSums[lane] = xx - ws;   // exclusive warp offsets
    }
    __syncthreads();

    double off0 = warpSums[wid] + wexcl;
    #pragma unroll
    for (int k = 0; k < 4; k++)
        pref[base + k] = off0 + v[k];
    __syncthreads();

    // d_t * log(suffix_sum[t]); suffix_sum[t] = pref[4095 - t]
    double c = 0.0;
    long long dtot = 0;
    #pragma unroll
    for (int k = 0; k < 4; k++) {
        int j = base + k;
        int d = dloc[k];
        dtot += d;
        if (d > 0) c += (double)d * log(pref[j]);
    }
    // subtract event-risk sum (fixed order across tid => deterministic)
    if (tid < GRID1) c -= g_partER[tid];

    #pragma unroll
    for (int off = 16; off > 0; off >>= 1) {
        c    += __shfl_down_sync(0xffffffffu, c, off);
        dtot += __shfl_down_sync(0xffffffffu, dtot, off);
    }
    if (lane == 0) { s_red[wid] = c; s_dred[wid] = dtot; }
    __syncthreads();
    if (wid == 0) {
        double cc = s_red[lane];
        long long dd = s_dred[lane];
        #pragma unroll
        for (int off = 16; off > 0; off >>= 1) {
            cc += __shfl_down_sync(0xffffffffu, cc, off);
            dd += __shfl_down_sync(0xffffffffu, dd, off);
        }
        if (lane == 0)
            out[0] = (dd > 0) ? (float)cc : 0.0f;
    }
    __syncthreads();

    // self-clean for the next graph replay
    #pragma unroll
    for (int i = tid; i < NBINS; i += THREADS1) {
        g_Sfix[i] = 0ull;
        g_D[i] = 0;
    }
    if (tid == 0)
        g_count = 0u;
}

// ---------------------------------------------------------------------------
extern "C" void kernel_launch(void* const* d_in, const int* in_sizes, int n_in,
                              void* d_out, int out_size)
{
    const float* risk  = (const float*)d_in[0];
    const int*   time_ = (const int*)d_in[1];
    const int*   event_= (const int*)d_in[2];
    float* out = (float*)d_out;
    int n = in_sizes[0];

    cox_fused_kernel<<<GRID1, THREADS1>>>(risk, time_, event_, out, n);
}

// round 14
// speedup vs baseline: 3.4081x; 1.0075x over previous
#include <cuda_runtime.h>
#include <cuda_bf16.h>
#include <math.h>

// CoxPHLoss without sorting, fused single kernel:
//   S[t]  = sum_{j: time_j == t} exp(risk_j)         (4096 buckets)
//   L[t]  = log( sum_{t' >= t} S[t'] )               (suffix logsum)
//   nll   = sum_t d_t * L[t] - sum_{i: event_i} risk_i
//
// Histogram: ONE packed 32-bit shared atomic per element:
//   v = rn(exp2(r*log2e + 11)) | (event << 25)
// The streaming loop is co-bound by MUFU.EX2 (~8 cyc/SMSP) and smem ATOMS
// (~2 cyc/lane); this round maximizes their overlap: GB300 has 152 SMs ->
// grid 304, 2-deep unrolled front-batched loads (MLP), and the fixed-point
// scale folded into the exp2 argument (drops one FMUL per element).
// Global combine: exact integer atomics (deterministic). Last block does the
// suffix scan + NLL and self-cleans (ticket pattern needs no co-residency).

#define NBINS    4096
#define GRID1    304            // 2 blocks/SM x 152 SMs (GB300)
#define THREADS1 1024
#define FIX_INV   4.8828125e-04         // 2^-11 exact
#define EXP_BIAS  11.0f                 // fold 2^11 into exp2 argument
#define LOG2E     1.44269504088896340736f
#define DSHIFT    25
#define SMASK     ((1u << DSHIFT) - 1u)

// Scratch (device globals; zero at load, self-cleaned per launch)
__device__ unsigned long long g_Sfix[NBINS];
__device__ int                g_D[NBINS];
__device__ double             g_partER[GRID1];
__device__ unsigned int       g_count;

__device__ __forceinline__ unsigned int fixexp(float r)
{
    return __float2uint_rn(exp2f(fmaf(r, LOG2E, EXP_BIAS)));
}

__global__ __launch_bounds__(THREADS1, 2)
void cox_fused_kernel(const float* __restrict__ risk,
                      const int* __restrict__ time_,
                      const int* __restrict__ event_,
                      float* __restrict__ out,
                      int n)
{
    __shared__ unsigned int s_P[NBINS];   // packed histogram (16 KB)
    __shared__ double pref[NBINS];        // final phase only (32 KB)
    __shared__ double s_red[32];
    __shared__ long long s_dred[32];
    __shared__ double warpSums[32];
    __shared__ unsigned int s_ticket;

    const int tid = threadIdx.x;
    const int bid = blockIdx.x;
    const int lane = tid & 31, wid = tid >> 5;

    #pragma unroll
    for (int i = tid; i < NBINS; i += THREADS1)
        s_P[i] = 0u;
    __syncthreads();

    // ---------------- Phase 1: streaming packed histogram ----------------
    double er = 0.0;   // sum of risk over events (this thread)

    const int nvec = n >> 2;
    const float4* r4 = reinterpret_cast<const float4*>(risk);
    const int4*   t4 = reinterpret_cast<const int4*>(time_);
    const int4*   e4 = reinterpret_cast<const int4*>(event_);

    const int gstride = GRID1 * THREADS1;
    const int gtid = bid * THREADS1 + tid;

    int i = gtid;
    // 2-deep unroll: issue all 6 vector loads before dependent math (MLP)
    for (; i + gstride < nvec; i += 2 * gstride) {
        float4 ra = r4[i];
        int4   ta = t4[i];
        int4   ea = e4[i];
        float4 rb = r4[i + gstride];
        int4   tb = t4[i + gstride];
        int4   eb = e4[i + gstride];

        int a0 = ta.x & (NBINS - 1), a1 = ta.y & (NBINS - 1);
        int a2 = ta.z & (NBINS - 1), a3 = ta.w & (NBINS - 1);
        int b0 = tb.x & (NBINS - 1), b1 = tb.y & (NBINS - 1);
        int b2 = tb.z & (NBINS - 1), b3 = tb.w & (NBINS - 1);

        unsigned int va0 = fixexp(ra.x), va1 = fixexp(ra.y);
        unsigned int va2 = fixexp(ra.z), va3 = fixexp(ra.w);
        unsigned int vb0 = fixexp(rb.x), vb1 = fixexp(rb.y);
        unsigned int vb2 = fixexp(rb.z), vb3 = fixexp(rb.w);

        if (ea.x) { va0 += (1u << DSHIFT); er += (double)ra.x; }
        if (ea.y) { va1 += (1u << DSHIFT); er += (double)ra.y; }
        if (ea.z) { va2 += (1u << DSHIFT); er += (double)ra.z; }
        if (ea.w) { va3 += (1u << DSHIFT); er += (double)ra.w; }
        if (eb.x) { vb0 += (1u << DSHIFT); er += (double)rb.x; }
        if (eb.y) { vb1 += (1u << DSHIFT); er += (double)rb.y; }
        if (eb.z) { vb2 += (1u << DSHIFT); er += (double)rb.z; }
        if (eb.w) { vb3 += (1u << DSHIFT); er += (double)rb.w; }

        atomicAdd(&s_P[a0], va0);
        atomicAdd(&s_P[a1], va1);
        atomicAdd(&s_P[a2], va2);
        atomicAdd(&s_P[a3], va3);
        atomicAdd(&s_P[b0], vb0);
        atomicAdd(&s_P[b1], vb1);
        atomicAdd(&s_P[b2], vb2);
        atomicAdd(&s_P[b3], vb3);
    }
    if (i < nvec) {
        float4 r = r4[i];
        int4   t = t4[i];
        int4   e = e4[i];
        int t0 = t.x & (NBINS - 1), t1 = t.y & (NBINS - 1);
        int t2 = t.z & (NBINS - 1), t3 = t.w & (NBINS - 1);
        unsigned int v0 = fixexp(r.x), v1 = fixexp(r.y);
        unsigned int v2 = fixexp(r.z), v3 = fixexp(r.w);
        if (e.x) { v0 += (1u << DSHIFT); er += (double)r.x; }
        if (e.y) { v1 += (1u << DSHIFT); er += (double)r.y; }
        if (e.z) { v2 += (1u << DSHIFT); er += (double)r.z; }
        if (e.w) { v3 += (1u << DSHIFT); er += (double)r.w; }
        atomicAdd(&s_P[t0], v0);
        atomicAdd(&s_P[t1], v1);
        atomicAdd(&s_P[t2], v2);
        atomicAdd(&s_P[t3], v3);
    }

    // scalar tail (n not multiple of 4)
    for (int j = (nvec << 2) + gtid; j < n; j += gstride) {
        float r = risk[j];
        int   t = time_[j] & (NBINS - 1);
        unsigned int v = fixexp(r);
        if (event_[j]) { v += (1u << DSHIFT); er += (double)r; }
        atomicAdd(&s_P[t], v);
    }

    // block-reduce er -> g_partER[bid]
    #pragma unroll
    for (int off = 16; off > 0; off >>= 1)
        er += __shfl_down_sync(0xffffffffu, er, off);
    if (lane == 0) s_red[wid] = er;
    __syncthreads();
    if (wid == 0) {
        double v = s_red[lane];
        #pragma unroll
        for (int off = 16; off > 0; off >>= 1)
            v += __shfl_down_sync(0xffffffffu, v, off);
        if (lane == 0) g_partER[bid] = v;
    }
    __syncthreads();

    // flush packed histogram -> global integer accumulators (deterministic)
    #pragma unroll
    for (int k = tid; k < NBINS; k += THREADS1) {
        unsigned int p = s_P[k];
        if (p) {
            unsigned int sfx = p & SMASK;
            int d = (int)(p >> DSHIFT);
            atomicAdd(&g_Sfix[k], (unsigned long long)sfx);
            if (d) atomicAdd(&g_D[k], d);
        }
    }

    // ---- last-block-done: final suffix scan + NLL + self-clean ----
    __threadfence();
    __syncthreads();
    if (tid == 0)
        s_ticket = atomicAdd(&g_count, 1u);
    __syncthreads();
    if (s_ticket != GRID1 - 1)
        return;

    // Last block: all other blocks' atomics visible.
    const int base = tid * 4;   // 4 reversed-index elements per thread

    double v[4];
    int dloc[4];
    double run = 0.0;
    #pragma unroll
    for (int k = 0; k < 4; k++) {
        int t = NBINS - 1 - (base + k);
        run += (double)g_Sfix[t] * FIX_INV;
        v[k] = run;
        dloc[k] = g_D[t];
    }
    double total = run;

    // warp inclusive scan of per-thread totals
    double x = total;
    #pragma unroll
    for (int off = 1; off < 32; off <<= 1) {
        double y = __shfl_up_sync(0xffffffffu, x, off);
        if (lane >= off) x += y;
    }
    double wexcl = x - total;
    if (lane == 31) warpSums[wid] = x;
    __syncthreads();

    if (wid == 0) {
        double ws = warpSums[lane];
        double xx = ws;
        #pragma unroll
        for (int off = 1; off < 32; off <<= 1) {
            double y = __shfl_up_sync(0xffffffffu, xx, off);
            if (lane >= off) xx += y;
        }
        warpSums[lane] = xx - ws;   // exclusive warp offsets
    }
    __syncthreads();

    double off0 = warpSums[wid] + wexcl;
    #pragma unroll
    for (int k = 0; k < 4; k++)
        pref[base + k] = off0 + v[k];
    __syncthreads();

    // d_t * log(suffix_sum[t]); suffix_sum[t] = pref[4095 - t]
    double c = 0.0;
    long long dtot = 0;
    #pragma unroll
    for (int k = 0; k < 4; k++) {
        int j = base + k;
        int d = dloc[k];
        dtot += d;
        if (d > 0) c += (double)d * log(pref[j]);
    }
    // subtract event-risk sum (fixed order across tid => deterministic)
    if (tid < GRID1) c -= g_partER[tid];

    #pragma unroll
    for (int off = 16; off > 0; off >>= 1) {
        c    += __shfl_down_sync(0xffffffffu, c, off);
        dtot += __shfl_down_sync(0xffffffffu, dtot, off);
    }
    if (lane == 0) { s_red[wid] = c; s_dred[wid] = dtot; }
    __syncthreads();
    if (wid == 0) {
        double cc = s_red[lane];
        long long dd = s_dred[lane];
        #pragma unroll
        for (int off = 16; off > 0; off >>= 1) {
            cc += __shfl_down_sync(0xffffffffu, cc, off);
            dd += __shfl_down_sync(0xffffffffu, dd, off);
        }
        if (lane == 0)
            out[0] = (dd > 0) ? (float)cc : 0.0f;
    }
    __syncthreads();

    // self-clean for the next graph replay
    #pragma unroll
    for (int k = tid; k < NBINS; k += THREADS1) {
        g_Sfix[k] = 0ull;
        g_D[k] = 0;
    }
    if (tid == 0)
        g_count = 0u;
}

// ---------------------------------------------------------------------------
extern "C" void kernel_launch(void* const* d_in, const int* in_sizes, int n_in,
                              void* d_out, int out_size)
{
    const float* risk  = (const float*)d_in[0];
    const int*   time_ = (const int*)d_in[1];
    const int*   event_= (const int*)d_in[2];
    float* out = (float*)d_out;
    int n = in_sizes[0];

    cox_fused_kernel<<<GRID1, THREADS1>>>(risk, time_, event_, out, n);
}

// round 16
// speedup vs baseline: 4.6940x; 1.3773x over previous
#include <cuda_runtime.h>
#include <cuda_bf16.h>
#include <math.h>

// CoxPHLoss without sorting, fused single kernel:
//   S[t]  = sum_{j: time_j == t} exp(risk_j)         (4096 buckets)
//   L[t]  = log( sum_{t' >= t} S[t'] )               (suffix logsum)
//   nll   = sum_t d_t * L[t] - sum_{i: event_i} risk_i
//
// Histogram: ONE packed 32-bit shared atomic per element:
//   v = fix11(exp(r)) | (event << 25)
// R15: dependency-chain shortening. Fixed-point conversion via magic-number
// FFMA+LOP (replaces 20-cyc F2I). exp computed hybrid: 5/8 elements on MUFU
// (__expf), 3/8 on the idle FMA pipe via degree-4 exp2 polynomial with
// exponent splice. Event-risk sum accumulated in float per thread (fixed
// order -> deterministic), widened to double at the block reduce.
// Global combine: exact integer atomics (deterministic). Last block does
// the suffix scan + NLL and self-cleans for graph replays.

#define NBINS    4096
#define GRID1    304            // 2 blocks/SM x 152 SMs (GB300)
#define THREADS1 1024
#define FIX_INV   4.8828125e-04         // 2^-11 exact
#define EXP_BIAS  11.0f                 // fold 2^11 into exp2 argument
#define LOG2E     1.44269504088896340736f
#define DSHIFT    25
#define SMASK     ((1u << DSHIFT) - 1u)
#define MAGIC     8388608.0f            // 2^23

// Scratch (device globals; zero at load, self-cleaned per launch)
__device__ unsigned long long g_Sfix[NBINS];
__device__ int                g_D[NBINS];
__device__ double             g_partER[GRID1];
__device__ unsigned int       g_count;

// MUFU path: exp via MUFU.EX2, fixed-point via magic-number round
__device__ __forceinline__ unsigned int fixexp_mufu(float r)
{
    float e = __expf(r);                      // FMUL + MUFU.EX2
    float m = fmaf(e, 2048.0f, MAGIC);        // FFMA, RN rounds to integer
    return __float_as_uint(m) & 0x007FFFFFu;  // LOP
}

// FMA-pipe path: exp2(r*log2e + 11) via degree-4 poly + exponent splice
__device__ __forceinline__ unsigned int fixexp_poly(float r)
{
    float t = fmaf(r, LOG2E, EXP_BIAS);       // t = log2(exp(r)*2^11)
    t = fminf(fmaxf(t, 0.5f), 22.5f);         // keep 2^t < 2^23 (magic-safe)
    float fi = floorf(t);
    float f  = t - fi;                        // f in [0,1)
    float p = fmaf(f, 0.00961804886f, 0.0555041087f);
    p = fmaf(f, p, 0.240226507f);
    p = fmaf(f, p, 0.693147180f);
    p = fmaf(f, p, 1.0f);                     // ~2^f, rel err ~1e-6
    int bits = __float_as_int(p) + (((int)fi) << 23);   // scale by 2^fi
    float val = __int_as_float(bits);         // exp(r)*2^11
    float m = fmaf(val, 1.0f, MAGIC);         // round to integer (RN)
    return __float_as_uint(m) & 0x007FFFFFu;
}

__global__ __launch_bounds__(THREADS1, 2)
void cox_fused_kernel(const float* __restrict__ risk,
                      const int* __restrict__ time_,
                      const int* __restrict__ event_,
                      float* __restrict__ out,
                      int n)
{
    __shared__ unsigned int s_P[NBINS];   // packed histogram (16 KB)
    __shared__ double pref[NBINS];        // final phase only (32 KB)
    __shared__ double s_red[32];
    __shared__ long long s_dred[32];
    __shared__ double warpSums[32];
    __shared__ unsigned int s_ticket;

    const int tid = threadIdx.x;
    const int bid = blockIdx.x;
    const int lane = tid & 31, wid = tid >> 5;

    #pragma unroll
    for (int i = tid; i < NBINS; i += THREADS1)
        s_P[i] = 0u;
    __syncthreads();

    // ---------------- Phase 1: streaming packed histogram ----------------
    float erf_ = 0.0f;   // per-thread event-risk sum (fixed order)

    const int nvec = n >> 2;
    const float4* r4 = reinterpret_cast<const float4*>(risk);
    const int4*   t4 = reinterpret_cast<const int4*>(time_);
    const int4*   e4 = reinterpret_cast<const int4*>(event_);

    const int gstride = GRID1 * THREADS1;
    const int gtid = bid * THREADS1 + tid;

    int i = gtid;
    // 2-deep unroll: front-batched loads; 5/8 elements on MUFU, 3/8 on FMA
    for (; i + gstride < nvec; i += 2 * gstride) {
        float4 ra = r4[i];
        int4   ta = t4[i];
        int4   ea = e4[i];
        float4 rb = r4[i + gstride];
        int4   tb = t4[i + gstride];
        int4   eb = e4[i + gstride];

        int a0 = ta.x & (NBINS - 1), a1 = ta.y & (NBINS - 1);
        int a2 = ta.z & (NBINS - 1), a3 = ta.w & (NBINS - 1);
        int b0 = tb.x & (NBINS - 1), b1 = tb.y & (NBINS - 1);
        int b2 = tb.z & (NBINS - 1), b3 = tb.w & (NBINS - 1);

        unsigned int va0 = fixexp_mufu(ra.x);
        unsigned int va1 = fixexp_poly(ra.y);
        unsigned int va2 = fixexp_mufu(ra.z);
        unsigned int va3 = fixexp_mufu(ra.w);
        unsigned int vb0 = fixexp_mufu(rb.x);
        unsigned int vb1 = fixexp_poly(rb.y);
        unsigned int vb2 = fixexp_mufu(rb.z);
        unsigned int vb3 = fixexp_poly(rb.w);

        if (ea.x) { va0 += (1u << DSHIFT); erf_ += ra.x; }
        if (ea.y) { va1 += (1u << DSHIFT); erf_ += ra.y; }
        if (ea.z) { va2 += (1u << DSHIFT); erf_ += ra.z; }
        if (ea.w) { va3 += (1u << DSHIFT); erf_ += ra.w; }
        if (eb.x) { vb0 += (1u << DSHIFT); erf_ += rb.x; }
        if (eb.y) { vb1 += (1u << DSHIFT); erf_ += rb.y; }
        if (eb.z) { vb2 += (1u << DSHIFT); erf_ += rb.z; }
        if (eb.w) { vb3 += (1u << DSHIFT); erf_ += rb.w; }

        atomicAdd(&s_P[a0], va0);
        atomicAdd(&s_P[a1], va1);
        atomicAdd(&s_P[a2], va2);
        atomicAdd(&s_P[a3], va3);
        atomicAdd(&s_P[b0], vb0);
        atomicAdd(&s_P[b1], vb1);
        atomicAdd(&s_P[b2], vb2);
        atomicAdd(&s_P[b3], vb3);
    }
    if (i < nvec) {
        float4 r = r4[i];
        int4   t = t4[i];
        int4   e = e4[i];
        int t0 = t.x & (NBINS - 1), t1 = t.y & (NBINS - 1);
        int t2 = t.z & (NBINS - 1), t3 = t.w & (NBINS - 1);
        unsigned int v0 = fixexp_mufu(r.x), v1 = fixexp_poly(r.y);
        unsigned int v2 = fixexp_mufu(r.z), v3 = fixexp_mufu(r.w);
        if (e.x) { v0 += (1u << DSHIFT); erf_ += r.x; }
        if (e.y) { v1 += (1u << DSHIFT); erf_ += r.y; }
        if (e.z) { v2 += (1u << DSHIFT); erf_ += r.z; }
        if (e.w) { v3 += (1u << DSHIFT); erf_ += r.w; }
        atomicAdd(&s_P[t0], v0);
        atomicAdd(&s_P[t1], v1);
        atomicAdd(&s_P[t2], v2);
        atomicAdd(&s_P[t3], v3);
    }

    // scalar tail (n not multiple of 4)
    for (int j = (nvec << 2) + gtid; j < n; j += gstride) {
        float r = risk[j];
        int   t = time_[j] & (NBINS - 1);
        unsigned int v = fixexp_mufu(r);
        if (event_[j]) { v += (1u << DSHIFT); erf_ += r; }
        atomicAdd(&s_P[t], v);
    }

    // block-reduce er (widen to double at reduce; fixed order) -> g_partER
    double er = (double)erf_;
    #pragma unroll
    for (int off = 16; off > 0; off >>= 1)
        er += __shfl_down_sync(0xffffffffu, er, off);
    if (lane == 0) s_red[wid] = er;
    __syncthreads();
    if (wid == 0) {
        double v = s_red[lane];
        #pragma unroll
        for (int off = 16; off > 0; off >>= 1)
            v += __shfl_down_sync(0xffffffffu, v, off);
        if (lane == 0) g_partER[bid] = v;
    }
    __syncthreads();

    // flush packed histogram -> global integer accumulators (deterministic)
    #pragma unroll
    for (int k = tid; k < NBINS; k += THREADS1) {
        unsigned int p = s_P[k];
        if (p) {
            unsigned int sfx = p & SMASK;
            int d = (int)(p >> DSHIFT);
            atomicAdd(&g_Sfix[k], (unsigned long long)sfx);
            if (d) atomicAdd(&g_D[k], d);
        }
    }

    // ---- last-block-done: final suffix scan + NLL + self-clean ----
    __threadfence();
    __syncthreads();
    if (tid == 0)
        s_ticket = atomicAdd(&g_count, 1u);
    __syncthreads();
    if (s_ticket != GRID1 - 1)
        return;

    // Last block: all other blocks' atomics visible.
    const int base = tid * 4;   // 4 reversed-index elements per thread

    double v[4];
    int dloc[4];
    double run = 0.0;
    #pragma unroll
    for (int k = 0; k < 4; k++) {
        int t = NBINS - 1 - (base + k);
        run += (double)g_Sfix[t] * FIX_INV;
        v[k] = run;
        dloc[k] = g_D[t];
    }
    double total = run;

    // warp inclusive scan of per-thread totals
    double x = total;
    #pragma unroll
    for (int off = 1; off < 32; off <<= 1) {
        double y = __shfl_up_sync(0xffffffffu, x, off);
        if (lane >= off) x += y;
    }
    double wexcl = x - total;
    if (lane == 31) warpSums[wid] = x;
    __syncthreads();

    if (wid == 0) {
        double ws = warpSums[lane];
        double xx = ws;
        #pragma unroll
        for (int off = 1; off < 32; off <<= 1) {
            double y = __shfl_up_sync(0xffffffffu, xx, off);
            if (lane >= off) xx += y;
        }
        warpSums[lane] = xx - ws;   // exclusive warp offsets
    }
    __syncthreads();

    double off0 = warpSums[wid] + wexcl;
    #pragma unroll
    for (int k = 0; k < 4; k++)
        pref[base + k] = off0 + v[k];
    __syncthreads();

    // d_t * log(suffix_sum[t]); suffix_sum[t] = pref[4095 - t]
    double c = 0.0;
    long long dtot = 0;
    #pragma unroll
    for (int k = 0; k < 4; k++) {
        int j = base + k;
        int d = dloc[k];
        dtot += d;
        if (d > 0) c += (double)d * log(pref[j]);
    }
    // subtract event-risk sum (fixed order across tid => deterministic)
    if (tid < GRID1) c -= g_partER[tid];

    #pragma unroll
    for (int off = 16; off > 0; off >>= 1) {
        c    += __shfl_down_sync(0xffffffffu, c, off);
        dtot += __shfl_down_sync(0xffffffffu, dtot, off);
    }
    if (lane == 0) { s_red[wid] = c; s_dred[wid] = dtot; }
    __syncthreads();
    if (wid == 0) {
        double cc = s_red[lane];
        long long dd = s_dred[lane];
        #pragma unroll
        for (int off = 16; off > 0; off >>= 1) {
            cc += __shfl_down_sync(0xffffffffu, cc, off);
            dd += __shfl_down_sync(0xffffffffu, dd, off);
        }
        if (lane == 0)
            out[0] = (dd > 0) ? (float)cc : 0.0f;
    }
    __syncthreads();

    // self-clean for the next graph replay
    #pragma unroll
    for (int k = tid; k < NBINS; k += THREADS1) {
        g_Sfix[k] = 0ull;
        g_D[k] = 0;
    }
    if (tid == 0)
        g_count = 0u;
}

// ---------------------------------------------------------------------------
extern "C" void kernel_launch(void* const* d_in, const int* in_sizes, int n_in,
                              void* d_out, int out_size)
{
    const float* risk  = (const float*)d_in[0];
    const int*   time_ = (const int*)d_in[1];
    const int*   event_= (const int*)d_in[2];
    float* out = (float*)d_out;
    int n = in_sizes[0];

    cox_fused_kernel<<<GRID1, THREADS1>>>(risk, time_, event_, out, n);
}